// round 14
// baseline (speedup 1.0000x reference)
#include <cuda_runtime.h>
#include <math_constants.h>

#define N_PRE 8192
#define N_CUR 16384
#define KNN   8
#define NTHREADS 256

#define P1    32                  // partitions over pre (k1), 256 wide
#define TILE1 (N_PRE / P1)        // 256
#define P2    64                  // partitions over cur (k2), 256 wide
#define TILE2 (N_CUR / P2)        // 256
#define NCHUNK 256                // fine chunks over cur (64 wide)
#define CHUNK  (N_CUR / NCHUNK)   // 64
#define CAP   64
#define FWARPS 8
#define QB    4                   // queries per thread in min passes
#define K1BLK (P1 * (N_CUR / (NTHREADS * QB)))   // 32*16 = 512
#define K2BLK (P2 * (N_PRE / (NTHREADS * QB)))   // 64*8  = 512
#define RECBLK (N_CUR / FWARPS)                  // 2048
#define THRBLK (N_PRE / NTHREADS)                // 32

// Scratch (device globals; no allocations allowed)
__device__ int      g_cur2pre[N_CUR];
__device__ float    g_p1_min[P1 * N_CUR];    // [part][cur]  (coalesced stores)
__device__ float    g_cmin[NCHUNK * N_PRE];  // [chunk][pre] (coalesced stores)
__device__ float    g_T[N_PRE];
__device__ unsigned g_cmask[N_PRE * 8];      // 256-bit qualifying-chunk mask / query
__device__ float4   g_prep[N_PRE];           // packed pre: (x,y,z,|p|^2)
__device__ float4   g_curp[N_CUR];           // packed cur: (x,y,z,|c|^2)

// ---- packed f32x2 helpers ---------------------------------------------------
__device__ __forceinline__ unsigned long long packf2(float a, float b) {
    unsigned long long r;
    asm("mov.b64 %0, {%1,%2};" : "=l"(r) : "f"(a), "f"(b));
    return r;
}
__device__ __forceinline__ unsigned long long fma2(unsigned long long a,
                                                   unsigned long long b,
                                                   unsigned long long c) {
    unsigned long long d;
    asm("fma.rn.f32x2 %0, %1, %2, %3;" : "=l"(d) : "l"(a), "l"(b), "l"(c));
    return d;
}
__device__ __forceinline__ void unpackf2(unsigned long long v, float& lo, float& hi) {
    asm("mov.b64 {%0,%1}, %2;" : "=f"(lo), "=f"(hi) : "l"(v));
}

// key(q, c) = fmaf(m2z, cz, fmaf(m2y, cy, fmaf(m2x, cx, |c|^2))), m2* = -2*q*.
// Per-lane IEEE fma order identical in packed and scalar recompute -> bitwise
// equal across kernels.

// ---------------------------------------------------------------------------
// Launch 1: merged index-free min passes (R11 config: 1024 uniform blocks,
// 128-iter mainloops, QB=4 queries/thread, COALESCED stores).
//  blocks [0, 512):    k1 — min over a 256-wide PRE tile for 1024 cur queries
//  blocks [512, 1024): k2 — four 64-wide chunk minima over a 256-wide CUR tile
//                      for 1024 pre queries
// ---------------------------------------------------------------------------
__global__ __launch_bounds__(NTHREADS, 5)
void k_minpass(const float* __restrict__ pre, const float* __restrict__ cur) {
    __shared__ ulonglong2 tXY[128], tZN[128];
    const int tid = threadIdx.x;
    const int bid = blockIdx.x;

    if (bid < K1BLK) {
        // ---------------- k1: cur -> pre partition minima ----------------
        const int part = bid & (P1 - 1);
        const int yq   = bid >> 5;                    // 0..15
        const int base = part * TILE1;
        if (tid < TILE1 / 2) {
            int t0 = base + 2 * tid, t1 = t0 + 1;
            float x0 = pre[t0],             x1 = pre[t1];
            float y0 = pre[N_PRE + t0],     y1 = pre[N_PRE + t1];
            float z0 = pre[2 * N_PRE + t0], z1 = pre[2 * N_PRE + t1];
            float n0 = fmaf(z0, z0, fmaf(y0, y0, x0 * x0));
            float n1 = fmaf(z1, z1, fmaf(y1, y1, x1 * x1));
            tXY[tid] = make_ulonglong2(packf2(x0, x1), packf2(y0, y1));
            tZN[tid] = make_ulonglong2(packf2(z0, z1), packf2(n0, n1));
            if (yq == 0) {
                g_prep[t0] = make_float4(x0, y0, z0, n0);
                g_prep[t1] = make_float4(x1, y1, z1, n1);
            }
        }
        __syncthreads();

        unsigned long long qx[QB], qy[QB], qz[QB];
        int j[QB];
#pragma unroll
        for (int q = 0; q < QB; ++q) {
            j[q] = yq * (NTHREADS * QB) + q * NTHREADS + tid;
            float vx = -2.0f * cur[j[q]];
            float vy = -2.0f * cur[N_CUR + j[q]];
            float vz = -2.0f * cur[2 * N_CUR + j[q]];
            qx[q] = packf2(vx, vx); qy[q] = packf2(vy, vy); qz[q] = packf2(vz, vz);
        }

        float m0[QB], m1[QB];
#pragma unroll
        for (int q = 0; q < QB; ++q) { m0[q] = CUDART_INF_F; m1[q] = CUDART_INF_F; }

#pragma unroll 4
        for (int p = 0; p < TILE1 / 2; ++p) {
            const ulonglong2 xy = tXY[p], zn = tZN[p];
#pragma unroll
            for (int q = 0; q < QB; ++q) {
                unsigned long long k = fma2(qz[q], zn.x, fma2(qy[q], xy.y, fma2(qx[q], xy.x, zn.y)));
                float lo, hi;
                unpackf2(k, lo, hi);
                m0[q] = fminf(m0[q], lo);
                m1[q] = fminf(m1[q], hi);
            }
        }
#pragma unroll
        for (int q = 0; q < QB; ++q)
            g_p1_min[part * N_CUR + j[q]] = fminf(m0[q], m1[q]);   // coalesced
    } else {
        // ---------------- k2: pre -> cur 64-wide chunk minima ----------------
        const int b    = bid - K1BLK;
        const int part = b & (P2 - 1);
        const int yq   = b >> 6;                      // 0..7
        const int base = part * TILE2;
        if (tid < TILE2 / 2) {
            int t0 = base + 2 * tid, t1 = t0 + 1;
            float x0 = cur[t0],             x1 = cur[t1];
            float y0 = cur[N_CUR + t0],     y1 = cur[N_CUR + t1];
            float z0 = cur[2 * N_CUR + t0], z1 = cur[2 * N_CUR + t1];
            float n0 = fmaf(z0, z0, fmaf(y0, y0, x0 * x0));
            float n1 = fmaf(z1, z1, fmaf(y1, y1, x1 * x1));
            tXY[tid] = make_ulonglong2(packf2(x0, x1), packf2(y0, y1));
            tZN[tid] = make_ulonglong2(packf2(z0, z1), packf2(n0, n1));
            if (yq == 0) {
                g_curp[t0] = make_float4(x0, y0, z0, n0);
                g_curp[t1] = make_float4(x1, y1, z1, n1);
            }
        }
        __syncthreads();

        unsigned long long qx[QB], qy[QB], qz[QB];
        int idx[QB];
#pragma unroll
        for (int q = 0; q < QB; ++q) {
            idx[q] = yq * (NTHREADS * QB) + q * NTHREADS + tid;
            float vx = -2.0f * pre[idx[q]];
            float vy = -2.0f * pre[N_PRE + idx[q]];
            float vz = -2.0f * pre[2 * N_PRE + idx[q]];
            qx[q] = packf2(vx, vx); qy[q] = packf2(vy, vy); qz[q] = packf2(vz, vz);
        }

#pragma unroll
        for (int c = 0; c < 4; ++c) {                 // 4 chunks of 64 cands
            float m0[QB], m1[QB];
#pragma unroll
            for (int q = 0; q < QB; ++q) { m0[q] = CUDART_INF_F; m1[q] = CUDART_INF_F; }
#pragma unroll 4
            for (int p = c * 32; p < (c + 1) * 32; ++p) {
                const ulonglong2 xy = tXY[p], zn = tZN[p];
#pragma unroll
                for (int q = 0; q < QB; ++q) {
                    unsigned long long k = fma2(qz[q], zn.x, fma2(qy[q], xy.y, fma2(qx[q], xy.x, zn.y)));
                    float lo, hi;
                    unpackf2(k, lo, hi);
                    m0[q] = fminf(m0[q], lo);
                    m1[q] = fminf(m1[q], hi);
                }
            }
            const int ch = part * 4 + c;
#pragma unroll
            for (int q = 0; q < QB; ++q)
                g_cmin[ch * N_PRE + idx[q]] = fminf(m0[q], m1[q]);   // coalesced
        }
    }
}

// ---------------------------------------------------------------------------
// Launch 2 (combo):
//  blocks [0, 2048): k1 argmin recovery, warp per cur query (as R11).
//  blocks [2048, 2080): threshold, THREAD per pre query with coalesced reads:
//    pass 1: T = 8th-smallest of 256 chunk minima (register top-8 list);
//    pass 2: build the 256-bit qualifying-chunk mask (min <= T) -> g_cmask.
// ---------------------------------------------------------------------------
__global__ __launch_bounds__(NTHREADS)
void k_combo(const float* __restrict__ cur) {
    if (blockIdx.x < RECBLK) {
        const int w    = threadIdx.x >> 5;
        const int lane = threadIdx.x & 31;
        const int j    = blockIdx.x * FWARPS + w;       // cur query

        const float pm = g_p1_min[lane * N_CUR + j];
        float gm = pm;
#pragma unroll
        for (int off = 16; off > 0; off >>= 1)
            gm = fminf(gm, __shfl_xor_sync(0xFFFFFFFFu, gm, off));
        const unsigned owners = __ballot_sync(0xFFFFFFFFu, pm == gm);
        const int opart = __ffs(owners) - 1;

        const float m2x = -2.0f * cur[j];
        const float m2y = -2.0f * cur[N_CUR + j];
        const float m2z = -2.0f * cur[2 * N_CUR + j];
        const int base = opart * TILE1;
        int found = -1;
#pragma unroll
        for (int t = 0; t < TILE1; t += 32) {
            if (found >= 0) break;                      // uniform
            const float4 c = g_prep[base + t + lane];
            const float key = fmaf(m2z, c.z, fmaf(m2y, c.y, fmaf(m2x, c.x, c.w)));
            unsigned m = __ballot_sync(0xFFFFFFFFu, key == gm);
            if (m) found = base + t + (__ffs(m) - 1);
        }
        if (lane == 0) g_cur2pre[j] = found;
    } else {
        const int i = (blockIdx.x - RECBLK) * NTHREADS + threadIdx.x;  // pre query
        // pass 1: top-8 smallest of the 256 chunk minima (coalesced reads)
        float d[KNN];
#pragma unroll
        for (int k = 0; k < KNN; ++k) d[k] = CUDART_INF_F;
#pragma unroll 8
        for (int ch = 0; ch < NCHUNK; ++ch) {
            float v = g_cmin[ch * N_PRE + i];
            if (v < d[KNN - 1]) {
                d[KNN - 1] = v;
#pragma unroll
                for (int s = KNN - 1; s > 0; --s) {
                    if (d[s] < d[s - 1]) { float t = d[s]; d[s] = d[s - 1]; d[s - 1] = t; }
                }
            }
        }
        const float T = d[KNN - 1];
        g_T[i] = T;
        // pass 2: qualifying-chunk bitmask
#pragma unroll
        for (int s = 0; s < 8; ++s) {
            unsigned m = 0;
#pragma unroll 8
            for (int b = 0; b < 32; ++b) {
                float v = g_cmin[(s * 32 + b) * N_PRE + i];
                m |= (v <= T) ? (1u << b) : 0u;
            }
            g_cmask[i * 8 + s] = m;
        }
    }
}

// ---------------------------------------------------------------------------
// Launch 3: filter + final, warp per pre query. Reads the precomputed 256-bit
// chunk mask (one 32B segment), scans ONLY qualifying 64-wide chunks
// (generically exactly 8 -> 512 candidates), admits key<=T via ballot/popc
// into smem, exact top-8 via lexicographic warp-argmin, then epilogue.
// ---------------------------------------------------------------------------
__global__ __launch_bounds__(NTHREADS)
void k_filter_final(const float* __restrict__ pre, const float* __restrict__ ups,
                    float* __restrict__ out) {
    __shared__ float sk[FWARPS][CAP];
    __shared__ int   si[FWARPS][CAP];
    const int w    = threadIdx.x >> 5;
    const int lane = threadIdx.x & 31;
    const int i    = blockIdx.x * FWARPS + w;

    const float m2x = -2.0f * pre[i];
    const float m2y = -2.0f * pre[N_PRE + i];
    const float m2z = -2.0f * pre[2 * N_PRE + i];
    const float T   = g_T[i];

    unsigned mw = (lane < 8) ? g_cmask[i * 8 + lane] : 0u;   // one 32B segment

    int cnt = 0;
#pragma unroll
    for (int s = 0; s < 8; ++s) {
        unsigned msk = __shfl_sync(0xFFFFFFFFu, mw, s);
        while (msk) {
            const int p = __ffs(msk) - 1;
            msk &= msk - 1;
            const int base = (s * 32 + p) * CHUNK;
#pragma unroll
            for (int t = 0; t < CHUNK; t += 32) {
                const float4 c = g_curp[base + t + lane];
                const float key = fmaf(m2z, c.z, fmaf(m2y, c.y, fmaf(m2x, c.x, c.w)));
                const bool adm = (key <= T);
                unsigned m = __ballot_sync(0xFFFFFFFFu, adm);
                if (m) {
                    int pos = cnt + __popc(m & ((1u << lane) - 1u));
                    if (adm && pos < CAP) { sk[w][pos] = key; si[w][pos] = base + t + lane; }
                    cnt += __popc(m);
                }
            }
        }
    }
    cnt = min(cnt, CAP);

    float c0 = (lane < cnt)      ? sk[w][lane]      : CUDART_INF_F;
    int   x0 = (lane < cnt)      ? si[w][lane]      : 0x7FFFFFFF;
    float c1 = (lane + 32 < cnt) ? sk[w][lane + 32] : CUDART_INF_F;
    int   x1 = (lane + 32 < cnt) ? si[w][lane + 32] : 0x7FFFFFFF;

    int   sel  = 0;
    float selk = CUDART_INF_F;
#pragma unroll
    for (int r = 0; r < KNN; ++r) {
        float mk = c0; int mi = x0;
        if (c1 < mk || (c1 == mk && x1 < mi)) { mk = c1; mi = x1; }
#pragma unroll
        for (int off = 16; off > 0; off >>= 1) {
            float ok = __shfl_down_sync(0xFFFFFFFFu, mk, off);
            int   oi = __shfl_down_sync(0xFFFFFFFFu, mi, off);
            if (ok < mk || (ok == mk && oi < mi)) { mk = ok; mi = oi; }
        }
        const int   wi = __shfl_sync(0xFFFFFFFFu, mi, 0);
        const float wk = __shfl_sync(0xFFFFFFFFu, mk, 0);
        if (lane == r) { sel = wi; selk = wk; }
        if (x0 == wi) c0 = CUDART_INF_F;
        if (x1 == wi) c1 = CUDART_INF_F;
    }

    const float px = pre[i];
    const float py = pre[N_PRE + i];
    const float pz = pre[2 * N_PRE + i];

    float val = 0.0f;
    if (lane < KNN && selk < CUDART_INF_F) {
        const int j = sel;
        const float4 c = g_curp[j];
        float dx = c.x - px, dy = c.y - py, dz = c.z - pz;
        float dist = sqrtf(fmaf(dz, dz, fmaf(dy, dy, dx * dx)));
        val = (g_cur2pre[j] == i) ? dist : 0.0f;
    }
#pragma unroll
    for (int off = 4; off > 0; off >>= 1)
        val += __shfl_down_sync(0xFFFFFFFFu, val, off);

    if (lane == 0) out[i] = val / ups[i];
}

// ---------------------------------------------------------------------------
extern "C" void kernel_launch(void* const* d_in, const int* in_sizes, int n_in,
                              void* d_out, int out_size) {
    const float* pre = (const float*)d_in[0];   // (1, 3, 8192)
    const float* cur = (const float*)d_in[1];   // (1, 3, 16384)
    const float* ups = (const float*)d_in[2];   // (1, 8192)
    float* out = (float*)d_out;                 // (1, 8192)

    k_minpass<<<K1BLK + K2BLK, NTHREADS>>>(pre, cur);      // 1024 blocks

    k_combo<<<RECBLK + THRBLK, NTHREADS>>>(cur);           // 2080 blocks

    k_filter_final<<<N_PRE / FWARPS, NTHREADS>>>(pre, ups, out);
}

// round 15
// speedup vs baseline: 1.5511x; 1.5511x over previous
#include <cuda_runtime.h>
#include <math_constants.h>

#define N_PRE 8192
#define N_CUR 16384
#define KNN   8
#define NTHREADS 256

#define P1    32                  // partitions over pre (k1), 256 wide
#define TILE1 (N_PRE / P1)        // 256
#define P2    64                  // partitions over cur (k2), 256 wide
#define TILE2 (N_CUR / P2)        // 256
#define NCHUNK 256                // fine chunks over cur (64 wide)
#define CHUNK  (N_CUR / NCHUNK)   // 64
#define CAP   64
#define FWARPS 8
#define QB    4                   // queries per thread in min passes
#define K1BLK (P1 * (N_CUR / (NTHREADS * QB)))   // 512
#define K2BLK (P2 * (N_PRE / (NTHREADS * QB)))   // 512
#define RECBLK (N_CUR / FWARPS)                  // 2048
#define THRQ   32                                // queries per thresh block
#define THRBLK (N_PRE / THRQ)                    // 256

// Scratch (device globals; no allocations allowed)
__device__ int      g_cur2pre[N_CUR];
__device__ float    g_p1_min[P1 * N_CUR];    // [part][cur]  (coalesced stores)
__device__ float    g_cmin[NCHUNK * N_PRE];  // [chunk][pre] (coalesced stores)
__device__ float    g_T[N_PRE];
__device__ unsigned g_cmask[N_PRE * 8];      // 256-bit qualifying-chunk mask
__device__ float4   g_prep[N_PRE];           // packed pre: (x,y,z,|p|^2)
__device__ float4   g_curp[N_CUR];           // packed cur: (x,y,z,|c|^2)

// ---- packed f32x2 helpers ---------------------------------------------------
__device__ __forceinline__ unsigned long long packf2(float a, float b) {
    unsigned long long r;
    asm("mov.b64 %0, {%1,%2};" : "=l"(r) : "f"(a), "f"(b));
    return r;
}
__device__ __forceinline__ unsigned long long fma2(unsigned long long a,
                                                   unsigned long long b,
                                                   unsigned long long c) {
    unsigned long long d;
    asm("fma.rn.f32x2 %0, %1, %2, %3;" : "=l"(d) : "l"(a), "l"(b), "l"(c));
    return d;
}
__device__ __forceinline__ void unpackf2(unsigned long long v, float& lo, float& hi) {
    asm("mov.b64 {%0,%1}, %2;" : "=f"(lo), "=f"(hi) : "l"(v));
}

// key(q, c) = fmaf(m2z, cz, fmaf(m2y, cy, fmaf(m2x, cx, |c|^2))), m2* = -2*q*.
// Per-lane IEEE fma order identical everywhere -> bitwise-equal recompute.

// ---------------------------------------------------------------------------
// Launch 1: merged index-free min passes (R11 config: 1024 uniform blocks,
// 128-iter mainloops, QB=4, coalesced stores). k2 now emits 64-wide chunk
// minima (4 chunks per 256-wide tile).
// ---------------------------------------------------------------------------
__global__ __launch_bounds__(NTHREADS, 5)
void k_minpass(const float* __restrict__ pre, const float* __restrict__ cur) {
    __shared__ ulonglong2 tXY[128], tZN[128];
    const int tid = threadIdx.x;
    const int bid = blockIdx.x;

    if (bid < K1BLK) {
        const int part = bid & (P1 - 1);
        const int yq   = bid >> 5;                    // 0..15
        const int base = part * TILE1;
        if (tid < TILE1 / 2) {
            int t0 = base + 2 * tid, t1 = t0 + 1;
            float x0 = pre[t0],             x1 = pre[t1];
            float y0 = pre[N_PRE + t0],     y1 = pre[N_PRE + t1];
            float z0 = pre[2 * N_PRE + t0], z1 = pre[2 * N_PRE + t1];
            float n0 = fmaf(z0, z0, fmaf(y0, y0, x0 * x0));
            float n1 = fmaf(z1, z1, fmaf(y1, y1, x1 * x1));
            tXY[tid] = make_ulonglong2(packf2(x0, x1), packf2(y0, y1));
            tZN[tid] = make_ulonglong2(packf2(z0, z1), packf2(n0, n1));
            if (yq == 0) {
                g_prep[t0] = make_float4(x0, y0, z0, n0);
                g_prep[t1] = make_float4(x1, y1, z1, n1);
            }
        }
        __syncthreads();

        unsigned long long qx[QB], qy[QB], qz[QB];
        int j[QB];
#pragma unroll
        for (int q = 0; q < QB; ++q) {
            j[q] = yq * (NTHREADS * QB) + q * NTHREADS + tid;
            float vx = -2.0f * cur[j[q]];
            float vy = -2.0f * cur[N_CUR + j[q]];
            float vz = -2.0f * cur[2 * N_CUR + j[q]];
            qx[q] = packf2(vx, vx); qy[q] = packf2(vy, vy); qz[q] = packf2(vz, vz);
        }

        float m0[QB], m1[QB];
#pragma unroll
        for (int q = 0; q < QB; ++q) { m0[q] = CUDART_INF_F; m1[q] = CUDART_INF_F; }

#pragma unroll 4
        for (int p = 0; p < TILE1 / 2; ++p) {
            const ulonglong2 xy = tXY[p], zn = tZN[p];
#pragma unroll
            for (int q = 0; q < QB; ++q) {
                unsigned long long k = fma2(qz[q], zn.x, fma2(qy[q], xy.y, fma2(qx[q], xy.x, zn.y)));
                float lo, hi;
                unpackf2(k, lo, hi);
                m0[q] = fminf(m0[q], lo);
                m1[q] = fminf(m1[q], hi);
            }
        }
#pragma unroll
        for (int q = 0; q < QB; ++q)
            g_p1_min[part * N_CUR + j[q]] = fminf(m0[q], m1[q]);   // coalesced
    } else {
        const int b    = bid - K1BLK;
        const int part = b & (P2 - 1);
        const int yq   = b >> 6;                      // 0..7
        const int base = part * TILE2;
        if (tid < TILE2 / 2) {
            int t0 = base + 2 * tid, t1 = t0 + 1;
            float x0 = cur[t0],             x1 = cur[t1];
            float y0 = cur[N_CUR + t0],     y1 = cur[N_CUR + t1];
            float z0 = cur[2 * N_CUR + t0], z1 = cur[2 * N_CUR + t1];
            float n0 = fmaf(z0, z0, fmaf(y0, y0, x0 * x0));
            float n1 = fmaf(z1, z1, fmaf(y1, y1, x1 * x1));
            tXY[tid] = make_ulonglong2(packf2(x0, x1), packf2(y0, y1));
            tZN[tid] = make_ulonglong2(packf2(z0, z1), packf2(n0, n1));
            if (yq == 0) {
                g_curp[t0] = make_float4(x0, y0, z0, n0);
                g_curp[t1] = make_float4(x1, y1, z1, n1);
            }
        }
        __syncthreads();

        unsigned long long qx[QB], qy[QB], qz[QB];
        int idx[QB];
#pragma unroll
        for (int q = 0; q < QB; ++q) {
            idx[q] = yq * (NTHREADS * QB) + q * NTHREADS + tid;
            float vx = -2.0f * pre[idx[q]];
            float vy = -2.0f * pre[N_PRE + idx[q]];
            float vz = -2.0f * pre[2 * N_PRE + idx[q]];
            qx[q] = packf2(vx, vx); qy[q] = packf2(vy, vy); qz[q] = packf2(vz, vz);
        }

#pragma unroll
        for (int c = 0; c < 4; ++c) {                 // 4 chunks of 64 cands
            float m0[QB], m1[QB];
#pragma unroll
            for (int q = 0; q < QB; ++q) { m0[q] = CUDART_INF_F; m1[q] = CUDART_INF_F; }
#pragma unroll 4
            for (int p = c * 32; p < (c + 1) * 32; ++p) {
                const ulonglong2 xy = tXY[p], zn = tZN[p];
#pragma unroll
                for (int q = 0; q < QB; ++q) {
                    unsigned long long k = fma2(qz[q], zn.x, fma2(qy[q], xy.y, fma2(qx[q], xy.x, zn.y)));
                    float lo, hi;
                    unpackf2(k, lo, hi);
                    m0[q] = fminf(m0[q], lo);
                    m1[q] = fminf(m1[q], hi);
                }
            }
            const int ch = part * 4 + c;
#pragma unroll
            for (int q = 0; q < QB; ++q)
                g_cmin[ch * N_PRE + idx[q]] = fminf(m0[q], m1[q]);   // coalesced
        }
    }
}

// ---------------------------------------------------------------------------
// Launch 2 (combo):
//  blocks [0, 2048): k1 argmin recovery, warp per cur query (R11 form).
//  blocks [2048, 2304): thresh — block owns 32 pre queries. 8 warps coalesced-
//    load all 256 chunk minima into smem (stride-33, conflict-free); warp 0
//    does thread-per-query top-8 from smem -> T + 256-bit chunk mask.
// ---------------------------------------------------------------------------
__global__ __launch_bounds__(NTHREADS)
void k_combo(const float* __restrict__ cur) {
    __shared__ float sm[NCHUNK * 33];                 // 33.8KB (thresh only)
    if (blockIdx.x < RECBLK) {
        const int w    = threadIdx.x >> 5;
        const int lane = threadIdx.x & 31;
        const int j    = blockIdx.x * FWARPS + w;     // cur query

        const float pm = g_p1_min[lane * N_CUR + j];
        float gm = pm;
#pragma unroll
        for (int off = 16; off > 0; off >>= 1)
            gm = fminf(gm, __shfl_xor_sync(0xFFFFFFFFu, gm, off));
        const unsigned owners = __ballot_sync(0xFFFFFFFFu, pm == gm);
        const int opart = __ffs(owners) - 1;

        const float m2x = -2.0f * cur[j];
        const float m2y = -2.0f * cur[N_CUR + j];
        const float m2z = -2.0f * cur[2 * N_CUR + j];
        const int base = opart * TILE1;
        int found = -1;
#pragma unroll
        for (int t = 0; t < TILE1; t += 32) {
            if (found >= 0) break;                    // uniform
            const float4 c = g_prep[base + t + lane];
            const float key = fmaf(m2z, c.z, fmaf(m2y, c.y, fmaf(m2x, c.x, c.w)));
            unsigned m = __ballot_sync(0xFFFFFFFFu, key == gm);
            if (m) found = base + t + (__ffs(m) - 1);
        }
        if (lane == 0) g_cur2pre[j] = found;
    } else {
        const int qbase = (blockIdx.x - RECBLK) * THRQ;
        const int w     = threadIdx.x >> 5;
        const int lane  = threadIdx.x & 31;

        // Cooperative coalesced load: warp w covers chunks [w*32, w*32+32).
#pragma unroll 8
        for (int c = 0; c < 32; ++c) {
            const int ch = w * 32 + c;
            sm[ch * 33 + lane] = g_cmin[ch * N_PRE + qbase + lane];
        }
        __syncthreads();

        if (threadIdx.x < THRQ) {                     // thread per query
            const int q = qbase + threadIdx.x;
            float d[KNN];
#pragma unroll
            for (int k = 0; k < KNN; ++k) d[k] = CUDART_INF_F;
#pragma unroll 8
            for (int ch = 0; ch < NCHUNK; ++ch) {
                float v = sm[ch * 33 + threadIdx.x];
                if (v < d[KNN - 1]) {
                    d[KNN - 1] = v;
#pragma unroll
                    for (int s = KNN - 1; s > 0; --s)
                        if (d[s] < d[s - 1]) { float t = d[s]; d[s] = d[s - 1]; d[s - 1] = t; }
                }
            }
            const float T = d[KNN - 1];
            g_T[q] = T;
#pragma unroll
            for (int s = 0; s < 8; ++s) {
                unsigned m = 0;
#pragma unroll 8
                for (int b = 0; b < 32; ++b)
                    m |= (sm[(s * 32 + b) * 33 + threadIdx.x] <= T) ? (1u << b) : 0u;
                g_cmask[q * 8 + s] = m;
            }
        }
    }
}

// ---------------------------------------------------------------------------
// Launch 3: filter + final, warp per pre query. Precomputed 256-bit chunk mask
// (one 32B read); scans ONLY qualifying 64-wide chunks (~8 -> ~512 cands);
// admits key<=T via ballot/popc into smem; exact top-8 via lexicographic
// warp-argmin; masked mean-distance epilogue.
// ---------------------------------------------------------------------------
__global__ __launch_bounds__(NTHREADS)
void k_filter_final(const float* __restrict__ pre, const float* __restrict__ ups,
                    float* __restrict__ out) {
    __shared__ float sk[FWARPS][CAP];
    __shared__ int   si[FWARPS][CAP];
    const int w    = threadIdx.x >> 5;
    const int lane = threadIdx.x & 31;
    const int i    = blockIdx.x * FWARPS + w;

    const float m2x = -2.0f * pre[i];
    const float m2y = -2.0f * pre[N_PRE + i];
    const float m2z = -2.0f * pre[2 * N_PRE + i];
    const float T   = g_T[i];

    unsigned mw = (lane < 8) ? g_cmask[i * 8 + lane] : 0u;

    int cnt = 0;
#pragma unroll
    for (int s = 0; s < 8; ++s) {
        unsigned msk = __shfl_sync(0xFFFFFFFFu, mw, s);
        while (msk) {
            const int p = __ffs(msk) - 1;
            msk &= msk - 1;
            const int base = (s * 32 + p) * CHUNK;
#pragma unroll
            for (int t = 0; t < CHUNK; t += 32) {
                const float4 c = g_curp[base + t + lane];
                const float key = fmaf(m2z, c.z, fmaf(m2y, c.y, fmaf(m2x, c.x, c.w)));
                const bool adm = (key <= T);
                unsigned m = __ballot_sync(0xFFFFFFFFu, adm);
                if (m) {
                    int pos = cnt + __popc(m & ((1u << lane) - 1u));
                    if (adm && pos < CAP) { sk[w][pos] = key; si[w][pos] = base + t + lane; }
                    cnt += __popc(m);
                }
            }
        }
    }
    cnt = min(cnt, CAP);

    float c0 = (lane < cnt)      ? sk[w][lane]      : CUDART_INF_F;
    int   x0 = (lane < cnt)      ? si[w][lane]      : 0x7FFFFFFF;
    float c1 = (lane + 32 < cnt) ? sk[w][lane + 32] : CUDART_INF_F;
    int   x1 = (lane + 32 < cnt) ? si[w][lane + 32] : 0x7FFFFFFF;

    int   sel  = 0;
    float selk = CUDART_INF_F;
#pragma unroll
    for (int r = 0; r < KNN; ++r) {
        float mk = c0; int mi = x0;
        if (c1 < mk || (c1 == mk && x1 < mi)) { mk = c1; mi = x1; }
#pragma unroll
        for (int off = 16; off > 0; off >>= 1) {
            float ok = __shfl_down_sync(0xFFFFFFFFu, mk, off);
            int   oi = __shfl_down_sync(0xFFFFFFFFu, mi, off);
            if (ok < mk || (ok == mk && oi < mi)) { mk = ok; mi = oi; }
        }
        const int   wi = __shfl_sync(0xFFFFFFFFu, mi, 0);
        const float wk = __shfl_sync(0xFFFFFFFFu, mk, 0);
        if (lane == r) { sel = wi; selk = wk; }
        if (x0 == wi) c0 = CUDART_INF_F;
        if (x1 == wi) c1 = CUDART_INF_F;
    }

    const float px = pre[i];
    const float py = pre[N_PRE + i];
    const float pz = pre[2 * N_PRE + i];

    float val = 0.0f;
    if (lane < KNN && selk < CUDART_INF_F) {
        const int j = sel;
        const float4 c = g_curp[j];
        float dx = c.x - px, dy = c.y - py, dz = c.z - pz;
        float dist = sqrtf(fmaf(dz, dz, fmaf(dy, dy, dx * dx)));
        val = (g_cur2pre[j] == i) ? dist : 0.0f;
    }
#pragma unroll
    for (int off = 4; off > 0; off >>= 1)
        val += __shfl_down_sync(0xFFFFFFFFu, val, off);

    if (lane == 0) out[i] = val / ups[i];
}

// ---------------------------------------------------------------------------
extern "C" void kernel_launch(void* const* d_in, const int* in_sizes, int n_in,
                              void* d_out, int out_size) {
    const float* pre = (const float*)d_in[0];   // (1, 3, 8192)
    const float* cur = (const float*)d_in[1];   // (1, 3, 16384)
    const float* ups = (const float*)d_in[2];   // (1, 8192)
    float* out = (float*)d_out;                 // (1, 8192)

    k_minpass<<<K1BLK + K2BLK, NTHREADS>>>(pre, cur);      // 1024 blocks

    k_combo<<<RECBLK + THRBLK, NTHREADS>>>(cur);           // 2304 blocks

    k_filter_final<<<N_PRE / FWARPS, NTHREADS>>>(pre, ups, out);
}

// round 16
// speedup vs baseline: 1.5685x; 1.0112x over previous
#include <cuda_runtime.h>
#include <math_constants.h>

#define N_PRE 8192
#define N_CUR 16384
#define KNN   8
#define NTHREADS 256

#define P1    32                  // partitions over pre (k1), 256 wide
#define TILE1 (N_PRE / P1)        // 256
#define P2    64                  // partitions over cur (k2), 256 wide
#define TILE2 (N_CUR / P2)        // 256
#define NCHUNK 256                // fine chunks over cur (64 wide)
#define CHUNK  (N_CUR / NCHUNK)   // 64
#define CAP   64
#define FWARPS 8
#define QB    4                   // queries per thread in min passes
#define K1BLK (P1 * (N_CUR / (NTHREADS * QB)))   // 512
#define K2BLK (P2 * (N_PRE / (NTHREADS * QB)))   // 512
#define THRQ   32                                // queries per thresh block
#define THRBLK (N_PRE / THRQ)                    // 256

// Scratch (device globals; no allocations allowed)
__device__ int      g_cur2pre[N_CUR];
__device__ float    g_p1_min[P1 * N_CUR];    // [part][cur]  (coalesced stores)
__device__ float    g_cmin[NCHUNK * N_PRE];  // [chunk][pre] (coalesced stores)
__device__ float    g_T[N_PRE];
__device__ unsigned g_cmask[N_PRE * 8];      // 256-bit qualifying-chunk mask
__device__ float4   g_prep[N_PRE];           // packed pre: (x,y,z,|p|^2)
__device__ float4   g_curp[N_CUR];           // packed cur: (x,y,z,|c|^2)

// ---- packed f32x2 helpers ---------------------------------------------------
__device__ __forceinline__ unsigned long long packf2(float a, float b) {
    unsigned long long r;
    asm("mov.b64 %0, {%1,%2};" : "=l"(r) : "f"(a), "f"(b));
    return r;
}
__device__ __forceinline__ unsigned long long fma2(unsigned long long a,
                                                   unsigned long long b,
                                                   unsigned long long c) {
    unsigned long long d;
    asm("fma.rn.f32x2 %0, %1, %2, %3;" : "=l"(d) : "l"(a), "l"(b), "l"(c));
    return d;
}
__device__ __forceinline__ void unpackf2(unsigned long long v, float& lo, float& hi) {
    asm("mov.b64 {%0,%1}, %2;" : "=f"(lo), "=f"(hi) : "l"(v));
}

// key(q, c) = fmaf(m2z, cz, fmaf(m2y, cy, fmaf(m2x, cx, |c|^2))), m2* = -2*q*.
// Per-lane IEEE fma order identical everywhere -> bitwise-equal recompute.

// ---------------------------------------------------------------------------
// Launch 1: merged index-free min passes (1024 uniform blocks, 128-iter
// mainloops, QB=4, coalesced stores). k2 emits 64-wide chunk minima.
// ---------------------------------------------------------------------------
__global__ __launch_bounds__(NTHREADS, 5)
void k_minpass(const float* __restrict__ pre, const float* __restrict__ cur) {
    __shared__ ulonglong2 tXY[128], tZN[128];
    const int tid = threadIdx.x;
    const int bid = blockIdx.x;

    if (bid < K1BLK) {
        const int part = bid & (P1 - 1);
        const int yq   = bid >> 5;                    // 0..15
        const int base = part * TILE1;
        if (tid < TILE1 / 2) {
            int t0 = base + 2 * tid, t1 = t0 + 1;
            float x0 = pre[t0],             x1 = pre[t1];
            float y0 = pre[N_PRE + t0],     y1 = pre[N_PRE + t1];
            float z0 = pre[2 * N_PRE + t0], z1 = pre[2 * N_PRE + t1];
            float n0 = fmaf(z0, z0, fmaf(y0, y0, x0 * x0));
            float n1 = fmaf(z1, z1, fmaf(y1, y1, x1 * x1));
            tXY[tid] = make_ulonglong2(packf2(x0, x1), packf2(y0, y1));
            tZN[tid] = make_ulonglong2(packf2(z0, z1), packf2(n0, n1));
            if (yq == 0) {
                g_prep[t0] = make_float4(x0, y0, z0, n0);
                g_prep[t1] = make_float4(x1, y1, z1, n1);
            }
        }
        __syncthreads();

        unsigned long long qx[QB], qy[QB], qz[QB];
        int j[QB];
#pragma unroll
        for (int q = 0; q < QB; ++q) {
            j[q] = yq * (NTHREADS * QB) + q * NTHREADS + tid;
            float vx = -2.0f * cur[j[q]];
            float vy = -2.0f * cur[N_CUR + j[q]];
            float vz = -2.0f * cur[2 * N_CUR + j[q]];
            qx[q] = packf2(vx, vx); qy[q] = packf2(vy, vy); qz[q] = packf2(vz, vz);
        }

        float m0[QB], m1[QB];
#pragma unroll
        for (int q = 0; q < QB; ++q) { m0[q] = CUDART_INF_F; m1[q] = CUDART_INF_F; }

#pragma unroll 4
        for (int p = 0; p < TILE1 / 2; ++p) {
            const ulonglong2 xy = tXY[p], zn = tZN[p];
#pragma unroll
            for (int q = 0; q < QB; ++q) {
                unsigned long long k = fma2(qz[q], zn.x, fma2(qy[q], xy.y, fma2(qx[q], xy.x, zn.y)));
                float lo, hi;
                unpackf2(k, lo, hi);
                m0[q] = fminf(m0[q], lo);
                m1[q] = fminf(m1[q], hi);
            }
        }
#pragma unroll
        for (int q = 0; q < QB; ++q)
            g_p1_min[part * N_CUR + j[q]] = fminf(m0[q], m1[q]);   // coalesced
    } else {
        const int b    = bid - K1BLK;
        const int part = b & (P2 - 1);
        const int yq   = b >> 6;                      // 0..7
        const int base = part * TILE2;
        if (tid < TILE2 / 2) {
            int t0 = base + 2 * tid, t1 = t0 + 1;
            float x0 = cur[t0],             x1 = cur[t1];
            float y0 = cur[N_CUR + t0],     y1 = cur[N_CUR + t1];
            float z0 = cur[2 * N_CUR + t0], z1 = cur[2 * N_CUR + t1];
            float n0 = fmaf(z0, z0, fmaf(y0, y0, x0 * x0));
            float n1 = fmaf(z1, z1, fmaf(y1, y1, x1 * x1));
            tXY[tid] = make_ulonglong2(packf2(x0, x1), packf2(y0, y1));
            tZN[tid] = make_ulonglong2(packf2(z0, z1), packf2(n0, n1));
            if (yq == 0) {
                g_curp[t0] = make_float4(x0, y0, z0, n0);
                g_curp[t1] = make_float4(x1, y1, z1, n1);
            }
        }
        __syncthreads();

        unsigned long long qx[QB], qy[QB], qz[QB];
        int idx[QB];
#pragma unroll
        for (int q = 0; q < QB; ++q) {
            idx[q] = yq * (NTHREADS * QB) + q * NTHREADS + tid;
            float vx = -2.0f * pre[idx[q]];
            float vy = -2.0f * pre[N_PRE + idx[q]];
            float vz = -2.0f * pre[2 * N_PRE + idx[q]];
            qx[q] = packf2(vx, vx); qy[q] = packf2(vy, vy); qz[q] = packf2(vz, vz);
        }

#pragma unroll
        for (int c = 0; c < 4; ++c) {                 // 4 chunks of 64 cands
            float m0[QB], m1[QB];
#pragma unroll
            for (int q = 0; q < QB; ++q) { m0[q] = CUDART_INF_F; m1[q] = CUDART_INF_F; }
#pragma unroll 4
            for (int p = c * 32; p < (c + 1) * 32; ++p) {
                const ulonglong2 xy = tXY[p], zn = tZN[p];
#pragma unroll
                for (int q = 0; q < QB; ++q) {
                    unsigned long long k = fma2(qz[q], zn.x, fma2(qy[q], xy.y, fma2(qx[q], xy.x, zn.y)));
                    float lo, hi;
                    unpackf2(k, lo, hi);
                    m0[q] = fminf(m0[q], lo);
                    m1[q] = fminf(m1[q], hi);
                }
            }
            const int ch = part * 4 + c;
#pragma unroll
            for (int q = 0; q < QB; ++q)
                g_cmin[ch * N_PRE + idx[q]] = fminf(m0[q], m1[q]);   // coalesced
        }
    }
}

// ---------------------------------------------------------------------------
// Launch 2: k1 argmin recovery, warp per cur query. NO smem -> full occupancy.
// ---------------------------------------------------------------------------
__global__ __launch_bounds__(NTHREADS)
void k_recover(const float* __restrict__ cur) {
    const int w    = threadIdx.x >> 5;
    const int lane = threadIdx.x & 31;
    const int j    = blockIdx.x * FWARPS + w;         // cur query

    const float pm = g_p1_min[lane * N_CUR + j];
    float gm = pm;
#pragma unroll
    for (int off = 16; off > 0; off >>= 1)
        gm = fminf(gm, __shfl_xor_sync(0xFFFFFFFFu, gm, off));
    const unsigned owners = __ballot_sync(0xFFFFFFFFu, pm == gm);
    const int opart = __ffs(owners) - 1;

    const float m2x = -2.0f * cur[j];
    const float m2y = -2.0f * cur[N_CUR + j];
    const float m2z = -2.0f * cur[2 * N_CUR + j];
    const int base = opart * TILE1;
    int found = -1;
#pragma unroll
    for (int t = 0; t < TILE1; t += 32) {
        if (found >= 0) break;                        // uniform
        const float4 c = g_prep[base + t + lane];
        const float key = fmaf(m2z, c.z, fmaf(m2y, c.y, fmaf(m2x, c.x, c.w)));
        unsigned m = __ballot_sync(0xFFFFFFFFu, key == gm);
        if (m) found = base + t + (__ffs(m) - 1);
    }
    if (lane == 0) g_cur2pre[j] = found;
}

// ---------------------------------------------------------------------------
// Launch 3: thresh — block owns 32 pre queries. 8 warps coalesced-load all 256
// chunk minima into smem (stride-33, conflict-free); then thread-per-query
// top-8 from smem -> T + 256-bit qualifying-chunk mask.
// ---------------------------------------------------------------------------
__global__ __launch_bounds__(NTHREADS)
void k_thresh() {
    __shared__ float sm[NCHUNK * 33];                 // ~33.8KB
    const int qbase = blockIdx.x * THRQ;
    const int w     = threadIdx.x >> 5;
    const int lane  = threadIdx.x & 31;

#pragma unroll 8
    for (int c = 0; c < 32; ++c) {
        const int ch = w * 32 + c;
        sm[ch * 33 + lane] = g_cmin[ch * N_PRE + qbase + lane];
    }
    __syncthreads();

    if (threadIdx.x < THRQ) {                         // thread per query
        const int q = qbase + threadIdx.x;
        float d[KNN];
#pragma unroll
        for (int k = 0; k < KNN; ++k) d[k] = CUDART_INF_F;
#pragma unroll 8
        for (int ch = 0; ch < NCHUNK; ++ch) {
            float v = sm[ch * 33 + threadIdx.x];
            if (v < d[KNN - 1]) {
                d[KNN - 1] = v;
#pragma unroll
                for (int s = KNN - 1; s > 0; --s)
                    if (d[s] < d[s - 1]) { float t = d[s]; d[s] = d[s - 1]; d[s - 1] = t; }
            }
        }
        const float T = d[KNN - 1];
        g_T[q] = T;
#pragma unroll
        for (int s = 0; s < 8; ++s) {
            unsigned m = 0;
#pragma unroll 8
            for (int b = 0; b < 32; ++b)
                m |= (sm[(s * 32 + b) * 33 + threadIdx.x] <= T) ? (1u << b) : 0u;
            g_cmask[q * 8 + s] = m;
        }
    }
}

// ---------------------------------------------------------------------------
// Launch 4: filter + final, warp per pre query. Precomputed 256-bit chunk mask
// (one 32B read); scans ONLY qualifying 64-wide chunks (~8 -> ~512 cands);
// admits key<=T via ballot/popc into smem; exact top-8 via lexicographic
// warp-argmin; masked mean-distance epilogue.
// ---------------------------------------------------------------------------
__global__ __launch_bounds__(NTHREADS)
void k_filter_final(const float* __restrict__ pre, const float* __restrict__ ups,
                    float* __restrict__ out) {
    __shared__ float sk[FWARPS][CAP];
    __shared__ int   si[FWARPS][CAP];
    const int w    = threadIdx.x >> 5;
    const int lane = threadIdx.x & 31;
    const int i    = blockIdx.x * FWARPS + w;

    const float m2x = -2.0f * pre[i];
    const float m2y = -2.0f * pre[N_PRE + i];
    const float m2z = -2.0f * pre[2 * N_PRE + i];
    const float T   = g_T[i];

    unsigned mw = (lane < 8) ? g_cmask[i * 8 + lane] : 0u;

    int cnt = 0;
#pragma unroll
    for (int s = 0; s < 8; ++s) {
        unsigned msk = __shfl_sync(0xFFFFFFFFu, mw, s);
        while (msk) {
            const int p = __ffs(msk) - 1;
            msk &= msk - 1;
            const int base = (s * 32 + p) * CHUNK;
#pragma unroll
            for (int t = 0; t < CHUNK; t += 32) {
                const float4 c = g_curp[base + t + lane];
                const float key = fmaf(m2z, c.z, fmaf(m2y, c.y, fmaf(m2x, c.x, c.w)));
                const bool adm = (key <= T);
                unsigned m = __ballot_sync(0xFFFFFFFFu, adm);
                if (m) {
                    int pos = cnt + __popc(m & ((1u << lane) - 1u));
                    if (adm && pos < CAP) { sk[w][pos] = key; si[w][pos] = base + t + lane; }
                    cnt += __popc(m);
                }
            }
        }
    }
    cnt = min(cnt, CAP);

    float c0 = (lane < cnt)      ? sk[w][lane]      : CUDART_INF_F;
    int   x0 = (lane < cnt)      ? si[w][lane]      : 0x7FFFFFFF;
    float c1 = (lane + 32 < cnt) ? sk[w][lane + 32] : CUDART_INF_F;
    int   x1 = (lane + 32 < cnt) ? si[w][lane + 32] : 0x7FFFFFFF;

    int   sel  = 0;
    float selk = CUDART_INF_F;
#pragma unroll
    for (int r = 0; r < KNN; ++r) {
        float mk = c0; int mi = x0;
        if (c1 < mk || (c1 == mk && x1 < mi)) { mk = c1; mi = x1; }
#pragma unroll
        for (int off = 16; off > 0; off >>= 1) {
            float ok = __shfl_down_sync(0xFFFFFFFFu, mk, off);
            int   oi = __shfl_down_sync(0xFFFFFFFFu, mi, off);
            if (ok < mk || (ok == mk && oi < mi)) { mk = ok; mi = oi; }
        }
        const int   wi = __shfl_sync(0xFFFFFFFFu, mi, 0);
        const float wk = __shfl_sync(0xFFFFFFFFu, mk, 0);
        if (lane == r) { sel = wi; selk = wk; }
        if (x0 == wi) c0 = CUDART_INF_F;
        if (x1 == wi) c1 = CUDART_INF_F;
    }

    const float px = pre[i];
    const float py = pre[N_PRE + i];
    const float pz = pre[2 * N_PRE + i];

    float val = 0.0f;
    if (lane < KNN && selk < CUDART_INF_F) {
        const int j = sel;
        const float4 c = g_curp[j];
        float dx = c.x - px, dy = c.y - py, dz = c.z - pz;
        float dist = sqrtf(fmaf(dz, dz, fmaf(dy, dy, dx * dx)));
        val = (g_cur2pre[j] == i) ? dist : 0.0f;
    }
#pragma unroll
    for (int off = 4; off > 0; off >>= 1)
        val += __shfl_down_sync(0xFFFFFFFFu, val, off);

    if (lane == 0) out[i] = val / ups[i];
}

// ---------------------------------------------------------------------------
extern "C" void kernel_launch(void* const* d_in, const int* in_sizes, int n_in,
                              void* d_out, int out_size) {
    const float* pre = (const float*)d_in[0];   // (1, 3, 8192)
    const float* cur = (const float*)d_in[1];   // (1, 3, 16384)
    const float* ups = (const float*)d_in[2];   // (1, 8192)
    float* out = (float*)d_out;                 // (1, 8192)

    k_minpass<<<K1BLK + K2BLK, NTHREADS>>>(pre, cur);      // 1024 blocks

    k_thresh<<<THRBLK, NTHREADS>>>();                      // 256 blocks

    k_recover<<<N_CUR / FWARPS, NTHREADS>>>(cur);          // 2048 blocks

    k_filter_final<<<N_PRE / FWARPS, NTHREADS>>>(pre, ups, out);
}